// round 1
// baseline (speedup 1.0000x reference)
#include <cuda_runtime.h>
#include <math.h>

#define S 4096
#define D 1024
#define H 16
#define HD 64

// Scratch (device globals — no allocation allowed in kernel_launch)
__device__ float g_Q[(size_t)S * D];
__device__ float g_K[(size_t)S * D];
__device__ float g_V[(size_t)S * D];
__device__ float g_O[(size_t)S * D];

// ---------------------------------------------------------------------------
// Tiled NT GEMM: Y[m,n] = sum_k X[m,k] * W[n,k]   (Y = X @ W^T)
// BM=BN=64, BK=16, 256 threads, 4x4 per thread. Optional RoPE epilogue.
// ---------------------------------------------------------------------------
#define BM 64
#define BN 64
#define BK 16
#define LDS_STRIDE 68   // 68*4B = 272B rows: keeps float4 16B-aligned, spreads banks

__device__ __forceinline__ void gemm_body(const float* __restrict__ X,
                                          const float* __restrict__ W,
                                          float* __restrict__ Y,
                                          const int* __restrict__ pos,
                                          bool doRope)
{
    __shared__ float Xs[BK][LDS_STRIDE];
    __shared__ float Ws[BK][LDS_STRIDE];

    const int tx = threadIdx.x;          // 0..15
    const int ty = threadIdx.y;          // 0..15
    const int t  = ty * 16 + tx;         // 0..255
    const int m0 = blockIdx.y * BM;
    const int n0 = blockIdx.x * BN;

    float acc[4][4];
#pragma unroll
    for (int i = 0; i < 4; i++)
#pragma unroll
        for (int j = 0; j < 4; j++) acc[i][j] = 0.0f;

    const int lrow = t >> 2;             // 0..63
    const int lkq  = (t & 3) << 2;       // 0,4,8,12

    for (int k0 = 0; k0 < D; k0 += BK) {
        // Cooperative load + transpose into smem (one float4 per thread per tile)
        float4 xa = *(const float4*)&X[(size_t)(m0 + lrow) * D + k0 + lkq];
        float4 wa = *(const float4*)&W[(size_t)(n0 + lrow) * D + k0 + lkq];
        Xs[lkq + 0][lrow] = xa.x; Xs[lkq + 1][lrow] = xa.y;
        Xs[lkq + 2][lrow] = xa.z; Xs[lkq + 3][lrow] = xa.w;
        Ws[lkq + 0][lrow] = wa.x; Ws[lkq + 1][lrow] = wa.y;
        Ws[lkq + 2][lrow] = wa.z; Ws[lkq + 3][lrow] = wa.w;
        __syncthreads();

#pragma unroll
        for (int kk = 0; kk < BK; kk++) {
            float4 a = *(const float4*)&Xs[kk][ty * 4];
            float4 b = *(const float4*)&Ws[kk][tx * 4];
            float av[4] = {a.x, a.y, a.z, a.w};
            float bv[4] = {b.x, b.y, b.z, b.w};
#pragma unroll
            for (int i = 0; i < 4; i++)
#pragma unroll
                for (int j = 0; j < 4; j++)
                    acc[i][j] = fmaf(av[i], bv[j], acc[i][j]);
        }
        __syncthreads();
    }

    const int m = m0 + ty * 4;
    const int n = n0 + tx * 4;

    if (doRope) {
        // freqs match jnp: 1 / theta^(e/64), e = even dim within head.
        // Computed in double then rounded — matches fp32 reference freqs ~1ulp.
        const int e0 = n & 63;          // n is a multiple of 4 -> even
        const int e1 = e0 + 2;
        const float f0 = (float)(1.0 / pow(10000.0, (double)e0 / 64.0));
        const float f1 = (float)(1.0 / pow(10000.0, (double)e1 / 64.0));
#pragma unroll
        for (int r = 0; r < 4; r++) {
            const float p = (float)pos[m + r];
            float s0, c0, s1, c1;
            sincosf(p * f0, &s0, &c0);    // accurate range reduction (angles up to ~4096 rad)
            sincosf(p * f1, &s1, &c1);
            float e = acc[r][0], o = acc[r][1];
            acc[r][0] = e * c0 - o * s0;
            acc[r][1] = e * s0 + o * c0;
            e = acc[r][2]; o = acc[r][3];
            acc[r][2] = e * c1 - o * s1;
            acc[r][3] = e * s1 + o * c1;
        }
    }

#pragma unroll
    for (int r = 0; r < 4; r++) {
        float4 v = make_float4(acc[r][0], acc[r][1], acc[r][2], acc[r][3]);
        *(float4*)&Y[(size_t)(m + r) * D + n] = v;
    }
}

__global__ __launch_bounds__(256) void qkv_kernel(const float* __restrict__ X,
                                                  const float* __restrict__ Wq,
                                                  const float* __restrict__ Wk,
                                                  const float* __restrict__ Wv,
                                                  const int* __restrict__ pos)
{
    const int z = blockIdx.z;
    const float* W = (z == 0) ? Wq : (z == 1) ? Wk : Wv;
    float* Y       = (z == 0) ? g_Q : (z == 1) ? g_K : g_V;
    gemm_body(X, W, Y, pos, z < 2);
}

__global__ __launch_bounds__(256) void out_kernel(const float* __restrict__ Wo,
                                                  float* __restrict__ Yout)
{
    gemm_body(g_O, Wo, Yout, (const int*)0, false);
}

// ---------------------------------------------------------------------------
// Flash attention, fp32, causal. One block = (64 q rows, 1 head).
// One thread owns one q row (q + acc in registers); K/V tiles in smem are
// read at warp-uniform addresses -> pure broadcast, FMA-issue-bound.
// ---------------------------------------------------------------------------
__global__ __launch_bounds__(64) void attn_kernel()
{
    __shared__ float Kt[64][64];
    __shared__ float Vt[64][64];

    const int t  = threadIdx.x;
    const int qt = (gridDim.x - 1) - blockIdx.x;   // heavy tiles first
    const int h  = blockIdx.y;
    const int qi = qt * 64 + t;

    const float* Qp = g_Q + (size_t)qi * D + h * HD;
    float4 qv[16];
#pragma unroll
    for (int i = 0; i < 16; i++) qv[i] = *(const float4*)(Qp + i * 4);

    float4 av[16];
#pragma unroll
    for (int i = 0; i < 16; i++) av[i] = make_float4(0.f, 0.f, 0.f, 0.f);

    float m = -1e30f, l = 0.0f;

#pragma unroll 1
    for (int kt = 0; kt <= qt; kt++) {
        const float* Kg = g_K + (size_t)(kt * 64) * D + h * HD;
        const float* Vg = g_V + (size_t)(kt * 64) * D + h * HD;
#pragma unroll
        for (int i = 0; i < 16; i++) {
            int idx = i * 64 + t;
            int row = idx >> 4;
            int c4  = (idx & 15) << 2;
            *(float4*)&Kt[row][c4] = *(const float4*)(Kg + (size_t)row * D + c4);
            *(float4*)&Vt[row][c4] = *(const float4*)(Vg + (size_t)row * D + c4);
        }
        __syncthreads();

        const bool last = (kt == qt);
#pragma unroll 1
        for (int jc = 0; jc < 4; jc++) {
            float sc[16];
            float cmax = -1e30f;
#pragma unroll
            for (int j = 0; j < 16; j++) {
                const int jj = jc * 16 + j;
                float s0 = 0.f, s1 = 0.f, s2 = 0.f, s3 = 0.f;
#pragma unroll
                for (int i = 0; i < 16; i++) {
                    float4 kv4 = *(const float4*)&Kt[jj][i * 4];
                    s0 = fmaf(qv[i].x, kv4.x, s0);
                    s1 = fmaf(qv[i].y, kv4.y, s1);
                    s2 = fmaf(qv[i].z, kv4.z, s2);
                    s3 = fmaf(qv[i].w, kv4.w, s3);
                }
                float s = ((s0 + s1) + (s2 + s3)) * 0.125f;   // 1/sqrt(64)
                if (last && (kt * 64 + jj) > qi) s = -1e30f;  // causal mask
                sc[j] = s;
                cmax = fmaxf(cmax, s);
            }
            const float mn    = fmaxf(m, cmax);
            const float scale = __expf(m - mn);
            m = mn;
            l *= scale;
#pragma unroll
            for (int i = 0; i < 16; i++) {
                av[i].x *= scale; av[i].y *= scale;
                av[i].z *= scale; av[i].w *= scale;
            }
#pragma unroll
            for (int j = 0; j < 16; j++) {
                const int jj = jc * 16 + j;
                const float p = __expf(sc[j] - mn);
                l += p;
#pragma unroll
                for (int i = 0; i < 16; i++) {
                    float4 vv = *(const float4*)&Vt[jj][i * 4];
                    av[i].x = fmaf(p, vv.x, av[i].x);
                    av[i].y = fmaf(p, vv.y, av[i].y);
                    av[i].z = fmaf(p, vv.z, av[i].z);
                    av[i].w = fmaf(p, vv.w, av[i].w);
                }
            }
        }
        __syncthreads();
    }

    const float inv = 1.0f / l;
    float* Op = g_O + (size_t)qi * D + h * HD;
#pragma unroll
    for (int i = 0; i < 16; i++) {
        float4 o = make_float4(av[i].x * inv, av[i].y * inv,
                               av[i].z * inv, av[i].w * inv);
        *(float4*)(Op + i * 4) = o;
    }
}

// ---------------------------------------------------------------------------
extern "C" void kernel_launch(void* const* d_in, const int* in_sizes, int n_in,
                              void* d_out, int out_size)
{
    (void)in_sizes; (void)n_in; (void)out_size;
    const float* x   = (const float*)d_in[0];
    const int*   pos = (const int*)  d_in[1];
    const float* Wq  = (const float*)d_in[2];
    const float* Wk  = (const float*)d_in[3];
    const float* Wv  = (const float*)d_in[4];
    const float* Wo  = (const float*)d_in[5];
    float* out = (float*)d_out;

    dim3 gblk(16, 16);
    qkv_kernel<<<dim3(D / BN, S / BM, 3), gblk>>>(x, Wq, Wk, Wv, pos);
    attn_kernel<<<dim3(S / 64, H), 64>>>();
    out_kernel<<<dim3(D / BN, S / BM, 1), gblk>>>(Wo, out);
}

// round 4
// speedup vs baseline: 3.4000x; 3.4000x over previous
#include <cuda_runtime.h>
#include <cuda_bf16.h>
#include <cstdint>
#include <math.h>

#define S 4096
#define D 1024
#define H 16
#define HD 64
typedef __nv_bfloat16 bf16;

// ---------------- device scratch -------------------------------------------
__device__ bf16 g_Xhi[(size_t)S * D], g_Xlo[(size_t)S * D];
__device__ bf16 g_Whi[4 * (size_t)D * D], g_Wlo[4 * (size_t)D * D];
__device__ bf16 g_Qhi[(size_t)S * D], g_Qlo[(size_t)S * D];
__device__ bf16 g_Khi[(size_t)S * D], g_Klo[(size_t)S * D];
__device__ bf16 g_Vhi[(size_t)S * D], g_Vlo[(size_t)S * D];
__device__ bf16 g_Ohi[(size_t)S * D], g_Olo[(size_t)S * D];
__device__ float g_cos[S * 32], g_sin[S * 32];

// ---------------- helpers ---------------------------------------------------
__device__ __forceinline__ uint32_t smem_u32(const void* p) {
    uint32_t a;
    asm("{ .reg .u64 t; cvta.to.shared.u64 t, %1; cvt.u32.u64 %0, t; }"
        : "=r"(a) : "l"(p));
    return a;
}

__device__ __forceinline__ void cp16(uint32_t saddr, const void* g) {
    asm volatile("cp.async.cg.shared.global [%0], [%1], 16;" :: "r"(saddr), "l"(g));
}

__device__ __forceinline__ void ldsm4(uint32_t a, uint32_t r[4]) {
    asm volatile("ldmatrix.sync.aligned.m8n8.x4.shared.b16 {%0,%1,%2,%3}, [%4];"
                 : "=r"(r[0]), "=r"(r[1]), "=r"(r[2]), "=r"(r[3]) : "r"(a));
}

__device__ __forceinline__ void ldsm4t(uint32_t a, uint32_t r[4]) {
    asm volatile("ldmatrix.sync.aligned.m8n8.x4.trans.shared.b16 {%0,%1,%2,%3}, [%4];"
                 : "=r"(r[0]), "=r"(r[1]), "=r"(r[2]), "=r"(r[3]) : "r"(a));
}

__device__ __forceinline__ void mma16816(float c[4], const uint32_t a[4],
                                         uint32_t b0, uint32_t b1) {
    asm volatile(
        "mma.sync.aligned.m16n8k16.row.col.f32.bf16.bf16.f32 "
        "{%0,%1,%2,%3}, {%4,%5,%6,%7}, {%8,%9}, {%0,%1,%2,%3};"
        : "+f"(c[0]), "+f"(c[1]), "+f"(c[2]), "+f"(c[3])
        : "r"(a[0]), "r"(a[1]), "r"(a[2]), "r"(a[3]), "r"(b0), "r"(b1));
}

__device__ __forceinline__ uint32_t pack_bf2(float a, float b) {
    bf16 ha = __float2bfloat16(a), hb = __float2bfloat16(b);
    return ((uint32_t)__bfloat16_as_ushort(hb) << 16) | __bfloat16_as_ushort(ha);
}

// ---------------- split / rope-table kernels --------------------------------
__device__ __forceinline__ void split_one(const float* src, bf16* hi, bf16* lo, size_t i) {
    float x = src[i];
    bf16 h = __float2bfloat16(x);
    hi[i] = h;
    lo[i] = __float2bfloat16(x - __bfloat162float(h));
}

__global__ void split_x_kernel(const float* __restrict__ x) {
    size_t i = (size_t)blockIdx.x * 256 + threadIdx.x;
    split_one(x, g_Xhi, g_Xlo, i);
}

__global__ void split_w_kernel(const float* __restrict__ Wq, const float* __restrict__ Wk,
                               const float* __restrict__ Wv, const float* __restrict__ Wo) {
    int z = blockIdx.z;
    const float* W = (z == 0) ? Wq : (z == 1) ? Wk : (z == 2) ? Wv : Wo;
    size_t i = (size_t)blockIdx.x * 256 + threadIdx.x;
    split_one(W, g_Whi + (size_t)z * D * D, g_Wlo + (size_t)z * D * D, i);
}

__global__ void rope_table_kernel(const int* __restrict__ pos) {
    int m = blockIdx.x;
    int i = threadIdx.x;  // pair index 0..31
    double f = pow(10000.0, -(double)(2 * i) / 64.0);
    float ang = (float)pos[m] * (float)f;
    float sv, cv;
    sincosf(ang, &sv, &cv);
    g_cos[m * 32 + i] = cv;
    g_sin[m * 32 + i] = sv;
}

// ---------------- split-bf16 HMMA GEMM:  Y = A @ B^T -------------------------
// CTA 128x128, 8 warps (2x4), k-chunk 32, double-buffered cp.async.
#define MM_SP    80                 // padded row bytes (32 bf16 + 16B pad)
#define MM_MAT   (128 * MM_SP)      // 10240 B
#define MM_STAGE (4 * MM_MAT)       // Ah, Al, Bh, Bl
#define MM_SMEM  (2 * MM_STAGE)     // 81920 B

__device__ __forceinline__ void mm_load_stage(uint32_t sb, int st, int c,
                                              const bf16* A_h, const bf16* A_l,
                                              const bf16* B_h, const bf16* B_l) {
    const bf16* srcs[4] = {A_h, A_l, B_h, B_l};
    int t = threadIdx.x;
#pragma unroll
    for (int i = 0; i < 8; i++) {
        int cid = t + i * 256;                 // 0..2047
        int mi = cid >> 9;                     // matrix 0..3
        int r  = (cid >> 2) & 127;             // row 0..127
        int q  = cid & 3;                      // 16B chunk 0..3
        const bf16* g = srcs[mi] + (size_t)r * D + c * 32 + q * 8;
        cp16(sb + st * MM_STAGE + mi * MM_MAT + r * MM_SP + q * 16, g);
    }
}

__device__ __forceinline__ void mm_stage_compute(uint32_t sb, int st, int wm, int wn,
                                                 int lane, float acc[4][4][4]) {
    uint32_t so = sb + st * MM_STAGE;
    const int lr = lane & 15, lc = lane >> 4;
#pragma unroll
    for (int ks = 0; ks < 2; ks++) {
        uint32_t af[4][4], bh[4][2], bl[4][2], t4[4];
#pragma unroll
        for (int i = 0; i < 4; i++)
            ldsm4(so + 0 * MM_MAT + (wm * 64 + i * 16 + lr) * MM_SP + ks * 32 + lc * 16, af[i]);
#pragma unroll
        for (int jj = 0; jj < 2; jj++) {
            ldsm4(so + 2 * MM_MAT + (wn * 32 + jj * 16 + lr) * MM_SP + ks * 32 + lc * 16, t4);
            bh[2 * jj][0] = t4[0]; bh[2 * jj][1] = t4[2];
            bh[2 * jj + 1][0] = t4[1]; bh[2 * jj + 1][1] = t4[3];
            ldsm4(so + 3 * MM_MAT + (wn * 32 + jj * 16 + lr) * MM_SP + ks * 32 + lc * 16, t4);
            bl[2 * jj][0] = t4[0]; bl[2 * jj][1] = t4[2];
            bl[2 * jj + 1][0] = t4[1]; bl[2 * jj + 1][1] = t4[3];
        }
#pragma unroll
        for (int i = 0; i < 4; i++)
#pragma unroll
            for (int j = 0; j < 4; j++) {
                mma16816(acc[i][j], af[i], bh[j][0], bh[j][1]);   // Ah*Bh
                mma16816(acc[i][j], af[i], bl[j][0], bl[j][1]);   // Ah*Bl
            }
#pragma unroll
        for (int i = 0; i < 4; i++)
            ldsm4(so + 1 * MM_MAT + (wm * 64 + i * 16 + lr) * MM_SP + ks * 32 + lc * 16, af[i]);
#pragma unroll
        for (int i = 0; i < 4; i++)
#pragma unroll
            for (int j = 0; j < 4; j++)
                mma16816(acc[i][j], af[i], bh[j][0], bh[j][1]);   // Al*Bh
    }
}

// mode 0: rope + bf16 hi/lo out; mode 1: bf16 hi/lo out; mode 2: fp32 out.
__device__ void mm_body(const bf16* Ah, const bf16* Al, const bf16* Bh, const bf16* Bl,
                        int mode, float* outF, bf16* outH, bf16* outL) {
    extern __shared__ char smem[];
    uint32_t sb = smem_u32(smem);
    const int tid = threadIdx.x, lane = tid & 31, wid = tid >> 5;
    const int wm = wid >> 2, wn = wid & 3;
    const int m0 = blockIdx.y * 128, n0 = blockIdx.x * 128;

    const bf16* A_h = Ah + (size_t)m0 * D;
    const bf16* A_l = Al + (size_t)m0 * D;
    const bf16* B_h = Bh + (size_t)n0 * D;
    const bf16* B_l = Bl + (size_t)n0 * D;

    float acc[4][4][4];
#pragma unroll
    for (int i = 0; i < 4; i++)
#pragma unroll
        for (int j = 0; j < 4; j++)
#pragma unroll
            for (int e = 0; e < 4; e++) acc[i][j][e] = 0.0f;

    mm_load_stage(sb, 0, 0, A_h, A_l, B_h, B_l);
    asm volatile("cp.async.commit_group;" ::: "memory");

#pragma unroll 1
    for (int c = 0; c < 32; c++) {
        int st = c & 1;
        if (c + 1 < 32) {
            mm_load_stage(sb, st ^ 1, c + 1, A_h, A_l, B_h, B_l);
            asm volatile("cp.async.commit_group;" ::: "memory");
            asm volatile("cp.async.wait_group 1;" ::: "memory");
        } else {
            asm volatile("cp.async.wait_group 0;" ::: "memory");
        }
        __syncthreads();
        mm_stage_compute(sb, st, wm, wn, lane, acc);
        __syncthreads();
    }

    const int g = lane >> 2, tig = lane & 3;
#pragma unroll
    for (int i = 0; i < 4; i++)
#pragma unroll
        for (int j = 0; j < 4; j++) {
            const int m = m0 + wm * 64 + i * 16 + g;
            const int n = n0 + wn * 32 + j * 8 + tig * 2;
#pragma unroll
            for (int rr = 0; rr < 2; rr++) {
                const int mm = m + rr * 8;
                float e = acc[i][j][rr * 2], o = acc[i][j][rr * 2 + 1];
                if (mode == 0) {
                    const int pidx = (n & 63) >> 1;
                    const float cv = g_cos[mm * 32 + pidx];
                    const float sv = g_sin[mm * 32 + pidx];
                    const float e2 = e * cv - o * sv;
                    const float o2 = e * sv + o * cv;
                    e = e2; o = o2;
                }
                if (mode == 2) {
                    *(float2*)(outF + (size_t)mm * D + n) = make_float2(e, o);
                } else {
                    bf16 he = __float2bfloat16(e), ho = __float2bfloat16(o);
                    float le = e - __bfloat162float(he);
                    float lo_ = o - __bfloat162float(ho);
                    *(uint32_t*)(outH + (size_t)mm * D + n) =
                        ((uint32_t)__bfloat16_as_ushort(ho) << 16) | __bfloat16_as_ushort(he);
                    *(uint32_t*)(outL + (size_t)mm * D + n) = pack_bf2(le, lo_);
                }
            }
        }
}

__global__ __launch_bounds__(256) void mm_qkv_kernel() {
    const int z = blockIdx.z;
    const bf16* Bh = g_Whi + (size_t)z * D * D;
    const bf16* Bl = g_Wlo + (size_t)z * D * D;
    bf16* oh = (z == 0) ? g_Qhi : (z == 1) ? g_Khi : g_Vhi;
    bf16* ol = (z == 0) ? g_Qlo : (z == 1) ? g_Klo : g_Vlo;
    mm_body(g_Xhi, g_Xlo, Bh, Bl, (z < 2) ? 0 : 1, (float*)0, oh, ol);
}

__global__ __launch_bounds__(256) void mm_out_kernel(float* __restrict__ out) {
    mm_body(g_Ohi, g_Olo, g_Whi + 3ull * D * D, g_Wlo + 3ull * D * D, 2, out, (bf16*)0, (bf16*)0);
}

// ---------------- HMMA flash attention --------------------------------------
// CTA = 64 q rows x 1 head, 4 warps (each m16). kv tiles of 64.
#define AT_SP   144                 // padded row bytes (64 bf16 = 128B + 16B pad)
#define AT_MAT  (64 * AT_SP)        // 9216 B
#define AT_SMEM (6 * AT_MAT)        // Qh Ql Kh Kl Vh Vl = 55296 B

// FIXED: a 64x64 bf16 tile is 128 bytes/row = 8 chunks of 16B -> 512 chunks.
__device__ __forceinline__ void at_load64(uint32_t sdst, const bf16* g) {
    int t = threadIdx.x;
#pragma unroll
    for (int i = 0; i < 4; i++) {
        int cid = t + i * 128;         // 0..511
        int r = cid >> 3;              // row 0..63
        int q = cid & 7;               // 16B chunk 0..7 (128B per row)
        cp16(sdst + r * AT_SP + q * 16, g + (size_t)r * D + q * 8);
    }
}

__global__ __launch_bounds__(128) void attn_kernel() {
    extern __shared__ char smem[];
    uint32_t sb = smem_u32(smem);
    const int tid = threadIdx.x, lane = tid & 31, w = tid >> 5;
    const int qt = (int)gridDim.x - 1 - (int)blockIdx.x;   // heavy first
    const int h = blockIdx.y;
    const int qbase = qt * 64;
    const int lr = lane & 15, lc = lane >> 4;
    const int g = lane >> 2, tig = lane & 3;

    at_load64(sb + 0 * AT_MAT, g_Qhi + (size_t)qbase * D + h * HD);
    at_load64(sb + 1 * AT_MAT, g_Qlo + (size_t)qbase * D + h * HD);
    asm volatile("cp.async.commit_group;" ::: "memory");
    asm volatile("cp.async.wait_group 0;" ::: "memory");
    __syncthreads();

    uint32_t qh[4][4], ql[4][4];
#pragma unroll
    for (int ks = 0; ks < 4; ks++) {
        ldsm4(sb + 0 * AT_MAT + (w * 16 + lr) * AT_SP + ks * 32 + lc * 16, qh[ks]);
        ldsm4(sb + 1 * AT_MAT + (w * 16 + lr) * AT_SP + ks * 32 + lc * 16, ql[ks]);
    }

    float o[8][4];
#pragma unroll
    for (int j = 0; j < 8; j++)
#pragma unroll
        for (int e = 0; e < 4; e++) o[j][e] = 0.0f;
    float m0r = -1e30f, m1r = -1e30f, l0 = 0.0f, l1 = 0.0f;

#pragma unroll 1
    for (int kt = 0; kt <= qt; kt++) {
        const size_t koff = (size_t)(kt * 64) * D + h * HD;
        __syncthreads();   // all warps done reading smem from previous tile
        at_load64(sb + 2 * AT_MAT, g_Khi + koff);
        at_load64(sb + 3 * AT_MAT, g_Klo + koff);
        at_load64(sb + 4 * AT_MAT, g_Vhi + koff);
        at_load64(sb + 5 * AT_MAT, g_Vlo + koff);
        asm volatile("cp.async.commit_group;" ::: "memory");
        asm volatile("cp.async.wait_group 0;" ::: "memory");
        __syncthreads();

        float s[8][4];
#pragma unroll
        for (int j = 0; j < 8; j++)
#pragma unroll
            for (int e = 0; e < 4; e++) s[j][e] = 0.0f;

        // --- S = (Qh+Ql)(Kh+Kl)^T, 3 combos ---
#pragma unroll
        for (int ks = 0; ks < 4; ks++) {
#pragma unroll
            for (int jj = 0; jj < 4; jj++) {
                uint32_t t4[4], u4[4];
                ldsm4(sb + 2 * AT_MAT + (jj * 16 + lr) * AT_SP + ks * 32 + lc * 16, t4);
                ldsm4(sb + 3 * AT_MAT + (jj * 16 + lr) * AT_SP + ks * 32 + lc * 16, u4);
                mma16816(s[2 * jj],     qh[ks], t4[0], t4[2]);
                mma16816(s[2 * jj],     qh[ks], u4[0], u4[2]);
                mma16816(s[2 * jj],     ql[ks], t4[0], t4[2]);
                mma16816(s[2 * jj + 1], qh[ks], t4[1], t4[3]);
                mma16816(s[2 * jj + 1], qh[ks], u4[1], u4[3]);
                mma16816(s[2 * jj + 1], ql[ks], t4[1], t4[3]);
            }
        }

        // --- scale + causal mask (diag tile only) ---
        const bool diag = (kt == qt);
#pragma unroll
        for (int j = 0; j < 8; j++)
#pragma unroll
            for (int e = 0; e < 4; e++) {
                float v = s[j][e] * 0.125f;
                if (diag) {
                    const int kvc = kt * 64 + j * 8 + tig * 2 + (e & 1);
                    const int qr  = qbase + w * 16 + g + ((e >> 1) << 3);
                    if (kvc > qr) v = -1e30f;
                }
                s[j][e] = v;
            }

        // --- online softmax ---
        float mx0 = -1e30f, mx1 = -1e30f;
#pragma unroll
        for (int j = 0; j < 8; j++) {
            mx0 = fmaxf(mx0, fmaxf(s[j][0], s[j][1]));
            mx1 = fmaxf(mx1, fmaxf(s[j][2], s[j][3]));
        }
        mx0 = fmaxf(mx0, __shfl_xor_sync(0xffffffffu, mx0, 1));
        mx0 = fmaxf(mx0, __shfl_xor_sync(0xffffffffu, mx0, 2));
        mx1 = fmaxf(mx1, __shfl_xor_sync(0xffffffffu, mx1, 1));
        mx1 = fmaxf(mx1, __shfl_xor_sync(0xffffffffu, mx1, 2));
        const float nm0 = fmaxf(m0r, mx0), nm1 = fmaxf(m1r, mx1);
        const float sc0 = __expf(m0r - nm0), sc1 = __expf(m1r - nm1);
        m0r = nm0; m1r = nm1;
        l0 *= sc0; l1 *= sc1;
#pragma unroll
        for (int j = 0; j < 8; j++) {
            o[j][0] *= sc0; o[j][1] *= sc0;
            o[j][2] *= sc1; o[j][3] *= sc1;
        }
#pragma unroll
        for (int j = 0; j < 8; j++) {
            s[j][0] = __expf(s[j][0] - nm0); s[j][1] = __expf(s[j][1] - nm0);
            s[j][2] = __expf(s[j][2] - nm1); s[j][3] = __expf(s[j][3] - nm1);
            l0 += s[j][0] + s[j][1];
            l1 += s[j][2] + s[j][3];
        }

        // --- O += (Ph+Pl)(Vh+Vl), 3 combos; V^T via ldmatrix.trans ---
#pragma unroll
        for (int ks = 0; ks < 4; ks++) {
            uint32_t pa[4], pl[4];
            {
                float r0, r1, r2, r3, r4, r5, r6, r7;
                bf16 b;
                b = __float2bfloat16(s[2 * ks][0]); r0 = s[2 * ks][0] - __bfloat162float(b);
                bf16 b1v = __float2bfloat16(s[2 * ks][1]); r1 = s[2 * ks][1] - __bfloat162float(b1v);
                pa[0] = ((uint32_t)__bfloat16_as_ushort(b1v) << 16) | __bfloat16_as_ushort(b);
                b = __float2bfloat16(s[2 * ks][2]); r2 = s[2 * ks][2] - __bfloat162float(b);
                b1v = __float2bfloat16(s[2 * ks][3]); r3 = s[2 * ks][3] - __bfloat162float(b1v);
                pa[1] = ((uint32_t)__bfloat16_as_ushort(b1v) << 16) | __bfloat16_as_ushort(b);
                b = __float2bfloat16(s[2 * ks + 1][0]); r4 = s[2 * ks + 1][0] - __bfloat162float(b);
                b1v = __float2bfloat16(s[2 * ks + 1][1]); r5 = s[2 * ks + 1][1] - __bfloat162float(b1v);
                pa[2] = ((uint32_t)__bfloat16_as_ushort(b1v) << 16) | __bfloat16_as_ushort(b);
                b = __float2bfloat16(s[2 * ks + 1][2]); r6 = s[2 * ks + 1][2] - __bfloat162float(b);
                b1v = __float2bfloat16(s[2 * ks + 1][3]); r7 = s[2 * ks + 1][3] - __bfloat162float(b1v);
                pa[3] = ((uint32_t)__bfloat16_as_ushort(b1v) << 16) | __bfloat16_as_ushort(b);
                pl[0] = pack_bf2(r0, r1); pl[1] = pack_bf2(r2, r3);
                pl[2] = pack_bf2(r4, r5); pl[3] = pack_bf2(r6, r7);
            }
#pragma unroll
            for (int jj = 0; jj < 4; jj++) {
                uint32_t t4[4], u4[4];
                ldsm4t(sb + 4 * AT_MAT + (ks * 16 + lr) * AT_SP + jj * 32 + lc * 16, t4);
                ldsm4t(sb + 5 * AT_MAT + (ks * 16 + lr) * AT_SP + jj * 32 + lc * 16, u4);
                mma16816(o[2 * jj],     pa, t4[0], t4[1]);
                mma16816(o[2 * jj],     pa, u4[0], u4[1]);
                mma16816(o[2 * jj],     pl, t4[0], t4[1]);
                mma16816(o[2 * jj + 1], pa, t4[2], t4[3]);
                mma16816(o[2 * jj + 1], pa, u4[2], u4[3]);
                mma16816(o[2 * jj + 1], pl, t4[2], t4[3]);
            }
        }
    }

    // --- finalize ---
    l0 += __shfl_xor_sync(0xffffffffu, l0, 1);
    l0 += __shfl_xor_sync(0xffffffffu, l0, 2);
    l1 += __shfl_xor_sync(0xffffffffu, l1, 1);
    l1 += __shfl_xor_sync(0xffffffffu, l1, 2);
    const float i0 = 1.0f / l0, i1 = 1.0f / l1;

#pragma unroll
    for (int j = 0; j < 8; j++) {
        const int n = h * HD + j * 8 + tig * 2;
#pragma unroll
        for (int rr = 0; rr < 2; rr++) {
            const int mm = qbase + w * 16 + g + rr * 8;
            const float inv = rr ? i1 : i0;
            const float e = o[j][2 * rr] * inv;
            const float od = o[j][2 * rr + 1] * inv;
            bf16 he = __float2bfloat16(e), ho = __float2bfloat16(od);
            float le = e - __bfloat162float(he);
            float lo_ = od - __bfloat162float(ho);
            *(uint32_t*)(g_Ohi + (size_t)mm * D + n) =
                ((uint32_t)__bfloat16_as_ushort(ho) << 16) | __bfloat16_as_ushort(he);
            *(uint32_t*)(g_Olo + (size_t)mm * D + n) = pack_bf2(le, lo_);
        }
    }
}

// ---------------------------------------------------------------------------
extern "C" void kernel_launch(void* const* d_in, const int* in_sizes, int n_in,
                              void* d_out, int out_size) {
    (void)in_sizes; (void)n_in; (void)out_size;
    const float* x   = (const float*)d_in[0];
    const int*   pos = (const int*)  d_in[1];
    const float* Wq  = (const float*)d_in[2];
    const float* Wk  = (const float*)d_in[3];
    const float* Wv  = (const float*)d_in[4];
    const float* Wo  = (const float*)d_in[5];
    float* out = (float*)d_out;

    cudaFuncSetAttribute(mm_qkv_kernel, cudaFuncAttributeMaxDynamicSharedMemorySize, MM_SMEM);
    cudaFuncSetAttribute(mm_out_kernel, cudaFuncAttributeMaxDynamicSharedMemorySize, MM_SMEM);
    cudaFuncSetAttribute(attn_kernel, cudaFuncAttributeMaxDynamicSharedMemorySize, AT_SMEM);

    split_x_kernel<<<(S * D) / 256, 256>>>(x);
    split_w_kernel<<<dim3((D * D) / 256, 1, 4), 256>>>(Wq, Wk, Wv, Wo);
    rope_table_kernel<<<S, 32>>>(pos);

    mm_qkv_kernel<<<dim3(D / 128, S / 128, 3), 256, MM_SMEM>>>();
    attn_kernel<<<dim3(S / 64, H), 128, AT_SMEM>>>();
    mm_out_kernel<<<dim3(D / 128, S / 128, 1), 256, MM_SMEM>>>(out);
}